// round 1
// baseline (speedup 1.0000x reference)
#include <cuda_runtime.h>
#include <math.h>

#define NUM_WIRES 18
#define NBITS     18
#define BATCH     64
#define DIM       262144            // 2^18
#define CHUNK_BITS 14
#define CHUNK     16384             // 2^14
#define NCHUNK    16                // 2^(18-14)
#define PL_THREADS 512
#define PH_THREADS 256

// Ping-pong state buffers (128MB each). __device__ globals are the sanctioned scratch.
__device__ float2 g_buf0[BATCH * DIM];
__device__ float2 g_buf1[BATCH * DIM];
// Gate table: per (layer, wire): (cos(ty/2), sin(ty/2), cos(tz/2), sin(tz/2))
__device__ float4 g_gates[3 * NUM_WIRES];
// Expval partials: [batch][chunk][wire]
__device__ float g_partial[BATCH * NCHUNK * NUM_WIRES];

// ---------------------------------------------------------------------------
// helpers
// ---------------------------------------------------------------------------

// Apply fused RZ(tz)*RY(ty) to amplitude pair (a = bit0 branch, b = bit1 branch)
__device__ __forceinline__ void apply_gate(float2& a, float2& b, float4 g) {
    // RY: a' = c*a - s*b ; b' = s*a + c*b        (c=g.x, s=g.y, real)
    float ar = fmaf(g.x, a.x, -g.y * b.x);
    float ai = fmaf(g.x, a.y, -g.y * b.y);
    float br = fmaf(g.y, a.x,  g.x * b.x);
    float bi = fmaf(g.y, a.y,  g.x * b.y);
    // RZ: a'' = a' * (cz - i sz) ; b'' = b' * (cz + i sz)   (cz=g.z, sz=g.w)
    a.x = fmaf(g.z, ar,  g.w * ai);
    a.y = fmaf(g.z, ai, -g.w * ar);
    b.x = fmaf(g.z, br, -g.w * bi);
    b.y = fmaf(g.z, bi,  g.w * br);
}

// shared-memory XOR swizzle (kills bank conflicts for all stage patterns)
__device__ __forceinline__ int SW(int t) { return t ^ ((t >> 5) & 31); }

// inverse Gray code (prefix-xor from MSB) for values < 2^16
__device__ __forceinline__ int invgray(int t) {
    t ^= t >> 1; t ^= t >> 2; t ^= t >> 4; t ^= t >> 8;
    return t;
}

// ---------------------------------------------------------------------------
// prep: compute gate coefficient table from params (3,2,18)
// ---------------------------------------------------------------------------
__global__ void k_prep(const float* __restrict__ params) {
    int t = threadIdx.x;
    if (t < 3 * NUM_WIRES) {
        int layer = t / NUM_WIRES, w = t % NUM_WIRES;
        float ty = params[(layer * 2 + 0) * NUM_WIRES + w] * 0.5f;
        float tz = params[(layer * 2 + 1) * NUM_WIRES + w] * 0.5f;
        g_gates[t] = make_float4(cosf(ty), sinf(ty), cosf(tz), sinf(tz));
    }
}

// ---------------------------------------------------------------------------
// pass_high: gates on wires 0..3 (index bits 17..14). Register-only, in-place.
// Each thread owns 16 amplitudes strided by 2^14.
// ---------------------------------------------------------------------------
__global__ void k_pass_high(float2* __restrict__ buf, int layer) {
    int gid = blockIdx.x * blockDim.x + threadIdx.x;   // 64 * 2^14 threads
    int b = gid >> CHUNK_BITS;
    int u = gid & (CHUNK - 1);
    long base = (long)b * DIM + u;

    float2 x[16];
#pragma unroll
    for (int r = 0; r < 16; ++r) x[r] = buf[base + ((long)r << CHUNK_BITS)];

#pragma unroll
    for (int w = 0; w < 4; ++w) {
        float4 g = g_gates[layer * NUM_WIRES + w];
        int m = 8 >> w;                      // wire w <-> r-bit (3-w)
#pragma unroll
        for (int r = 0; r < 16; ++r)
            if (!(r & m)) apply_gate(x[r], x[r | m], g);
    }

#pragma unroll
    for (int r = 0; r < 16; ++r) buf[base + ((long)r << CHUNK_BITS)] = x[r];
}

// first variant: reads separate re/im arrays, writes interleaved float2
__global__ void k_pass_high_first(const float* __restrict__ sre,
                                  const float* __restrict__ sim,
                                  float2* __restrict__ out) {
    int gid = blockIdx.x * blockDim.x + threadIdx.x;
    int b = gid >> CHUNK_BITS;
    int u = gid & (CHUNK - 1);
    long base = (long)b * DIM + u;

    float2 x[16];
#pragma unroll
    for (int r = 0; r < 16; ++r) {
        long idx = base + ((long)r << CHUNK_BITS);
        x[r] = make_float2(sre[idx], sim[idx]);
    }
#pragma unroll
    for (int w = 0; w < 4; ++w) {
        float4 g = g_gates[w];               // layer 0
        int m = 8 >> w;
#pragma unroll
        for (int r = 0; r < 16; ++r)
            if (!(r & m)) apply_gate(x[r], x[r | m], g);
    }
#pragma unroll
    for (int r = 0; r < 16; ++r) out[base + ((long)r << CHUNK_BITS)] = x[r];
}

// ---------------------------------------------------------------------------
// pass_low: gates on wires 4..17 (bits 13..0) in shared memory, then the
// CNOT-ladder permutation (inverse-Gray scatter) on the write.
// last==true: skip state write, compute <Z_w> partials instead.
// ---------------------------------------------------------------------------
__global__ void k_pass_low(const float2* __restrict__ in,
                           float2* __restrict__ out,
                           int layer, int last) {
    extern __shared__ float2 sh[];           // 2^14 float2 = 128KB
    int tid = threadIdx.x;
    int b = blockIdx.x >> 4;
    int C = blockIdx.x & 15;                 // source chunk (bits 14..17)
    const float2* src = in + (long)b * DIM + ((long)C << CHUNK_BITS);
    const float4* gt = &g_gates[layer * NUM_WIRES];

    for (int t = tid; t < CHUNK; t += PL_THREADS) sh[SW(t)] = src[t];
    __syncthreads();

    // stage 1: bits 0..4  (wires 17..13)
    {
        float2 x[32];
        int base = tid * 32;
#pragma unroll
        for (int j = 0; j < 32; ++j) x[j] = sh[SW(base + j)];
#pragma unroll
        for (int p = 0; p < 5; ++p) {
            float4 g = gt[17 - p];
            int m = 1 << p;
#pragma unroll
            for (int j = 0; j < 32; ++j)
                if (!(j & m)) apply_gate(x[j], x[j | m], g);
        }
#pragma unroll
        for (int j = 0; j < 32; ++j) sh[SW(base + j)] = x[j];
    }
    __syncthreads();

    // stage 2: bits 5..9  (wires 12..8)
    {
        float2 x[32];
        int low5 = tid & 31;
        int high = tid >> 5;                 // bits 10..13
        int base = low5 | (high << 10);
#pragma unroll
        for (int j = 0; j < 32; ++j) x[j] = sh[SW(base | (j << 5))];
#pragma unroll
        for (int p = 0; p < 5; ++p) {
            float4 g = gt[12 - p];
            int m = 1 << p;
#pragma unroll
            for (int j = 0; j < 32; ++j)
                if (!(j & m)) apply_gate(x[j], x[j | m], g);
        }
#pragma unroll
        for (int j = 0; j < 32; ++j) sh[SW(base | (j << 5))] = x[j];
    }
    __syncthreads();

    // stage 3: bits 10..13 (wires 7..4) — 1024 groups, 2 per thread
    for (int gi = 0; gi < 2; ++gi) {
        int g10 = tid + gi * PL_THREADS;     // low 10 bits
        float2 x[16];
#pragma unroll
        for (int r = 0; r < 16; ++r) x[r] = sh[SW(g10 | (r << 10))];
#pragma unroll
        for (int p = 0; p < 4; ++p) {
            float4 g = gt[7 - p];
            int m = 1 << p;
#pragma unroll
            for (int r = 0; r < 16; ++r)
                if (!(r & m)) apply_gate(x[r], x[r | m], g);
        }
#pragma unroll
        for (int r = 0; r < 16; ++r) sh[SW(g10 | (r << 10))] = x[r];
    }
    __syncthreads();

    // CNOT-ladder permutation: dest = invgray18(src index)
    int pm = (__popc(C) & 1) ? (CHUNK - 1) : 0;
    int Cd = C; Cd ^= Cd >> 1; Cd ^= Cd >> 2;       // invgray4

    if (!last) {
        float2* dst = out + (long)b * DIM + ((long)Cd << CHUNK_BITS);
        for (int t = tid; t < CHUNK; t += PL_THREADS) {
            int d = invgray(t) ^ pm;
            dst[d] = sh[SW(t)];
        }
    } else {
        float acc[NUM_WIRES];
#pragma unroll
        for (int w = 0; w < NUM_WIRES; ++w) acc[w] = 0.0f;
        int hi = Cd << CHUNK_BITS;
        for (int t = tid; t < CHUNK; t += PL_THREADS) {
            float2 v = sh[SW(t)];
            float pr = v.x * v.x + v.y * v.y;
            int d = hi | (invgray(t) ^ pm);          // full 18-bit dest index
            unsigned pbits = __float_as_uint(pr);
#pragma unroll
            for (int w = 0; w < NUM_WIRES; ++w) {
                unsigned bit = (unsigned)(d >> (17 - w)) & 1u;
                acc[w] += __uint_as_float(pbits ^ (bit << 31));  // +pr / -pr
            }
        }
        // warp reduction
#pragma unroll
        for (int w = 0; w < NUM_WIRES; ++w)
#pragma unroll
            for (int o = 16; o; o >>= 1)
                acc[w] += __shfl_down_sync(0xFFFFFFFFu, acc[w], o);
        __syncthreads();                      // all sh reads above are done
        float* scratch = (float*)sh;          // reuse: 16 warps x 18
        int warp = tid >> 5, lane = tid & 31;
        if (lane == 0)
#pragma unroll
            for (int w = 0; w < NUM_WIRES; ++w) scratch[warp * NUM_WIRES + w] = acc[w];
        __syncthreads();
        if (tid < NUM_WIRES) {
            float s = 0.0f;
#pragma unroll
            for (int k = 0; k < PL_THREADS / 32; ++k) s += scratch[k * NUM_WIRES + tid];
            g_partial[(b * NCHUNK + C) * NUM_WIRES + tid] = s;
        }
    }
}

// ---------------------------------------------------------------------------
// head: feats @ head_w.T + head_b
// ---------------------------------------------------------------------------
__global__ void k_head(const float* __restrict__ head_w,
                       const float* __restrict__ head_b,
                       float* __restrict__ out) {
    int b = threadIdx.x;
    if (b < BATCH) {
        float s = head_b[0];
#pragma unroll
        for (int w = 0; w < NUM_WIRES; ++w) {
            float f = 0.0f;
#pragma unroll
            for (int c = 0; c < NCHUNK; ++c)
                f += g_partial[(b * NCHUNK + c) * NUM_WIRES + w];
            s = fmaf(f, head_w[w], s);
        }
        out[b] = s;
    }
}

// ---------------------------------------------------------------------------
extern "C" void kernel_launch(void* const* d_in, const int* in_sizes, int n_in,
                              void* d_out, int out_size) {
    const float* state_re = (const float*)d_in[0];
    const float* state_im = (const float*)d_in[1];
    const float* params   = (const float*)d_in[2];
    const float* head_w   = (const float*)d_in[3];
    const float* head_b   = (const float*)d_in[4];
    float* out = (float*)d_out;

    // 128KB dynamic shared for pass_low (idempotent; not a stream op)
    cudaFuncSetAttribute(k_pass_low, cudaFuncAttributeMaxDynamicSharedMemorySize,
                         CHUNK * (int)sizeof(float2));

    const int ph_blocks = (BATCH * CHUNK) / PH_THREADS;   // 4096
    const int pl_blocks = BATCH * NCHUNK;                 // 1024
    const int shmem = CHUNK * (int)sizeof(float2);        // 128KB

    k_prep<<<1, 64>>>(params);

    // layer 0
    k_pass_high_first<<<ph_blocks, PH_THREADS>>>(state_re, state_im, g_buf0);
    k_pass_low<<<pl_blocks, PL_THREADS, shmem>>>(g_buf0, g_buf1, 0, 0);
    // layer 1
    k_pass_high<<<ph_blocks, PH_THREADS>>>(g_buf1, 1);
    k_pass_low<<<pl_blocks, PL_THREADS, shmem>>>(g_buf1, g_buf0, 1, 0);
    // layer 2
    k_pass_high<<<ph_blocks, PH_THREADS>>>(g_buf0, 2);
    k_pass_low<<<pl_blocks, PL_THREADS, shmem>>>(g_buf0, g_buf1, 2, 1);  // expvals only

    k_head<<<1, 64>>>(head_w, head_b, out);
}